// round 4
// baseline (speedup 1.0000x reference)
#include <cuda_runtime.h>
#include <cuda_bf16.h>
#include <math.h>

// Problem constants
#define BB  4
#define TT  2048
#define DDM 512
#define HH  8
#define HDM 64
#define MM  (BB*TT)          // 8192 rows for all projection GEMMs

// ---------------------------------------------------------------------------
// Scratch (allowed: __device__ globals, no dynamic allocation)
// ---------------------------------------------------------------------------
static __device__ float g_qp [MM * DDM];                       // 16 MB
static __device__ float g_kp [MM * DDM];                       // 16 MB
static __device__ float g_vp [MM * DDM];                       // 16 MB
static __device__ float g_ctx[MM * DDM];                       // 16 MB
static __device__ float g_attn[(size_t)BB * HH * TT * TT];     // 537 MB

// Device-side buffer selection: keeps kernel_launch free of ALL non-launch
// CUDA APIs (no cudaGetSymbolAddress during graph capture).
// sel: 0 = use external pointer, 1 = g_qp, 2 = g_kp, 3 = g_vp, 4 = g_ctx
__device__ __forceinline__ const float* sel_src(int s, const float* ext) {
    switch (s) {
        case 1:  return g_qp;
        case 2:  return g_kp;
        case 3:  return g_vp;
        case 4:  return g_ctx;
        default: return ext;
    }
}
__device__ __forceinline__ float* sel_dst(int s, float* ext) {
    switch (s) {
        case 1:  return g_qp;
        case 2:  return g_kp;
        case 3:  return g_vp;
        case 4:  return g_ctx;
        default: return ext;
    }
}

// ---------------------------------------------------------------------------
// Kernel 1: C[8192,512] = A[8192,512] @ W[512,512] + bias
// Tiling: BM=128, BN=128, BK=8, 256 threads, 8x8 per thread (FMA-bound)
// ---------------------------------------------------------------------------
__global__ __launch_bounds__(256)
void mha_gemm512_bias(const float* __restrict__ Aext, int Asel,
                      const float* __restrict__ W,
                      const float* __restrict__ bias,
                      float* __restrict__ Cext, int Csel)
{
    const float* A = sel_src(Asel, Aext);
    float*       C = sel_dst(Csel, Cext);

    __shared__ float sA[8][128];   // transposed A tile: sA[k][m]
    __shared__ float sB[8][128];   // sB[k][n]

    const int tid = threadIdx.x;
    const int m0  = blockIdx.y * 128;
    const int n0  = blockIdx.x * 128;

    // loaders
    const int arow = tid >> 1;            // 0..127
    const int acol = (tid & 1) << 2;      // 0 or 4
    const int brow = tid >> 5;            // 0..7
    const int bcol = (tid & 31) << 2;     // 0..124

    const float* Ap = A + (size_t)(m0 + arow) * DDM + acol;
    const float* Wp = W + (size_t)brow * DDM + n0 + bcol;

    // compute mapping: 16x16 thread grid, each 8x8
    const int tr = (tid >> 4) << 3;       // 0..120
    const int tc = (tid & 15) << 3;       // 0..120

    float acc[8][8];
    #pragma unroll
    for (int i = 0; i < 8; i++)
        #pragma unroll
        for (int j = 0; j < 8; j++) acc[i][j] = 0.f;

    for (int k0 = 0; k0 < DDM; k0 += 8) {
        float4 av = *(const float4*)Ap;
        float4 bv = *(const float4*)Wp;
        sA[acol + 0][arow] = av.x;
        sA[acol + 1][arow] = av.y;
        sA[acol + 2][arow] = av.z;
        sA[acol + 3][arow] = av.w;
        *(float4*)&sB[brow][bcol] = bv;
        __syncthreads();

        #pragma unroll
        for (int kk = 0; kk < 8; kk++) {
            float ar[8], br[8];
            *(float4*)&ar[0] = *(const float4*)&sA[kk][tr];
            *(float4*)&ar[4] = *(const float4*)&sA[kk][tr + 4];
            *(float4*)&br[0] = *(const float4*)&sB[kk][tc];
            *(float4*)&br[4] = *(const float4*)&sB[kk][tc + 4];
            #pragma unroll
            for (int i = 0; i < 8; i++)
                #pragma unroll
                for (int j = 0; j < 8; j++)
                    acc[i][j] = fmaf(ar[i], br[j], acc[i][j]);
        }
        __syncthreads();
        Ap += 8;
        Wp += 8 * DDM;
    }

    float bvals[8];
    *(float4*)&bvals[0] = *(const float4*)&bias[n0 + tc];
    *(float4*)&bvals[4] = *(const float4*)&bias[n0 + tc + 4];

    #pragma unroll
    for (int i = 0; i < 8; i++) {
        float4 o0, o1;
        o0.x = acc[i][0] + bvals[0];
        o0.y = acc[i][1] + bvals[1];
        o0.z = acc[i][2] + bvals[2];
        o0.w = acc[i][3] + bvals[3];
        o1.x = acc[i][4] + bvals[4];
        o1.y = acc[i][5] + bvals[5];
        o1.z = acc[i][6] + bvals[6];
        o1.w = acc[i][7] + bvals[7];
        float* crow = C + (size_t)(m0 + tr + i) * DDM + n0 + tc;
        *(float4*)&crow[0] = o0;
        *(float4*)&crow[4] = o1;
    }
}

// ---------------------------------------------------------------------------
// Kernel 2: scores + softmax-over-heads.
// Block = (b, q-tile 32, k-tile 64). For each of the 8 heads compute
// S_h[32x64] = Qh @ Kh^T, keep all 8 in registers, then softmax across h
// per (q,k) element (scale 0.125 folded into exp) and write attn[b][h][q][k].
// ---------------------------------------------------------------------------
__global__ __launch_bounds__(256)
void mha_scores_softmax(void)
{
    __shared__ float sQ[32][64];
    __shared__ float sK[64][68];   // +4 pad to break row-stride bank conflicts

    const int tid = threadIdx.x;
    const int k0  = blockIdx.x * 64;
    const int q0  = blockIdx.y * 32;
    const int b   = blockIdx.z;

    const int tq  = tid >> 4;      // 0..15
    const int tk  = tid & 15;      // 0..15
    const int qi0 = tq << 1;       // thread owns rows qi0, qi0+1
                                   // thread owns cols tk+16j, j=0..3

    // loader mappings
    const int lqr = tid >> 3;            // 0..31
    const int lqc = (tid & 7) << 3;      // 0..56
    const int lkr = tid >> 2;            // 0..63
    const int lkc = (tid & 3) << 4;      // 0,16,32,48

    // smem row pointers (constant across heads)
    const float4* qr0 = (const float4*)&sQ[qi0][0];
    const float4* qr1 = (const float4*)&sQ[qi0 + 1][0];
    const float4* kr0 = (const float4*)&sK[tk      ][0];
    const float4* kr1 = (const float4*)&sK[tk + 16][0];
    const float4* kr2 = (const float4*)&sK[tk + 32][0];
    const float4* kr3 = (const float4*)&sK[tk + 48][0];

    float sv[8][2][4];   // raw (unscaled) scores for all 8 heads

    #pragma unroll
    for (int h = 0; h < 8; h++) {
        // load Q tile for head h
        {
            const float* src = g_qp + (size_t)(b * TT + q0 + lqr) * DDM + h * HDM + lqc;
            *(float4*)&sQ[lqr][lqc]     = *(const float4*)&src[0];
            *(float4*)&sQ[lqr][lqc + 4] = *(const float4*)&src[4];
        }
        // load K tile for head h
        {
            const float* src = g_kp + (size_t)(b * TT + k0 + lkr) * DDM + h * HDM + lkc;
            *(float4*)&sK[lkr][lkc]      = *(const float4*)&src[0];
            *(float4*)&sK[lkr][lkc + 4]  = *(const float4*)&src[4];
            *(float4*)&sK[lkr][lkc + 8]  = *(const float4*)&src[8];
            *(float4*)&sK[lkr][lkc + 12] = *(const float4*)&src[12];
        }
        __syncthreads();

        float a00=0.f,a01=0.f,a02=0.f,a03=0.f;
        float a10=0.f,a11=0.f,a12=0.f,a13=0.f;
        #pragma unroll 4
        for (int d4 = 0; d4 < 16; d4++) {
            float4 a0 = qr0[d4];
            float4 a1 = qr1[d4];
            float4 b0 = kr0[d4];
            float4 b1 = kr1[d4];
            float4 b2 = kr2[d4];
            float4 b3 = kr3[d4];
            a00 = fmaf(a0.x,b0.x,a00); a00 = fmaf(a0.y,b0.y,a00); a00 = fmaf(a0.z,b0.z,a00); a00 = fmaf(a0.w,b0.w,a00);
            a01 = fmaf(a0.x,b1.x,a01); a01 = fmaf(a0.y,b1.y,a01); a01 = fmaf(a0.z,b1.z,a01); a01 = fmaf(a0.w,b1.w,a01);
            a02 = fmaf(a0.x,b2.x,a02); a02 = fmaf(a0.y,b2.y,a02); a02 = fmaf(a0.z,b2.z,a02); a02 = fmaf(a0.w,b2.w,a02);
            a03 = fmaf(a0.x,b3.x,a03); a03 = fmaf(a0.y,b3.y,a03); a03 = fmaf(a0.z,b3.z,a03); a03 = fmaf(a0.w,b3.w,a03);
            a10 = fmaf(a1.x,b0.x,a10); a10 = fmaf(a1.y,b0.y,a10); a10 = fmaf(a1.z,b0.z,a10); a10 = fmaf(a1.w,b0.w,a10);
            a11 = fmaf(a1.x,b1.x,a11); a11 = fmaf(a1.y,b1.y,a11); a11 = fmaf(a1.z,b1.z,a11); a11 = fmaf(a1.w,b1.w,a11);
            a12 = fmaf(a1.x,b2.x,a12); a12 = fmaf(a1.y,b2.y,a12); a12 = fmaf(a1.z,b2.z,a12); a12 = fmaf(a1.w,b2.w,a12);
            a13 = fmaf(a1.x,b3.x,a13); a13 = fmaf(a1.y,b3.y,a13); a13 = fmaf(a1.z,b3.z,a13); a13 = fmaf(a1.w,b3.w,a13);
        }
        sv[h][0][0]=a00; sv[h][0][1]=a01; sv[h][0][2]=a02; sv[h][0][3]=a03;
        sv[h][1][0]=a10; sv[h][1][1]=a11; sv[h][1][2]=a12; sv[h][1][3]=a13;
        __syncthreads();   // smem reused by next head
    }

    // softmax over the HEAD axis (axis=1), scale 1/sqrt(64)=0.125 folded in
    #pragma unroll
    for (int i = 0; i < 2; i++) {
        #pragma unroll
        for (int j = 0; j < 4; j++) {
            float m = sv[0][i][j];
            #pragma unroll
            for (int h = 1; h < 8; h++) m = fmaxf(m, sv[h][i][j]);
            float p[8];
            float s = 0.f;
            #pragma unroll
            for (int h = 0; h < 8; h++) {
                p[h] = __expf((sv[h][i][j] - m) * 0.125f);
                s += p[h];
            }
            const float inv = 1.f / s;
            const int qg = q0 + qi0 + i;
            const int kg = k0 + tk + 16 * j;
            #pragma unroll
            for (int h = 0; h < 8; h++) {
                g_attn[((size_t)(b * 8 + h) * TT + qg) * TT + kg] = p[h] * inv;
            }
        }
    }
}

// ---------------------------------------------------------------------------
// Kernel 3: ctx[b,q,h,d] = sum_k attn[b,h,q,k] * vp[b,k,h,d]
// Batched GEMM per (b,h): [2048 x 2048] @ [2048 x 64].
// BM=128, BN=64, BK=16, 256 threads, 8x4 per thread.
// ---------------------------------------------------------------------------
__global__ __launch_bounds__(256)
void mha_ctx(void)
{
    __shared__ float sA[16][128];  // transposed attn tile: sA[k][m]
    __shared__ float sB[16][64];   // sB[k][n]

    const int tid = threadIdx.x;
    const int m0  = blockIdx.x * 128;
    const int bh  = blockIdx.y;
    const int b   = bh >> 3;
    const int h   = bh & 7;

    const float* Abase = g_attn + (size_t)bh * TT * TT;
    const float* Bbase = g_vp   + (size_t)b * TT * DDM + h * HDM;

    const int arow = tid >> 1;            // 0..127
    const int acol = (tid & 1) << 3;      // 0 or 8
    const int brow = tid >> 4;            // 0..15
    const int bcol = (tid & 15) << 2;     // 0..60

    const int tr = (tid >> 4) << 3;       // 0..120
    const int tc = (tid & 15) << 2;       // 0..60

    float acc[8][4];
    #pragma unroll
    for (int i = 0; i < 8; i++)
        #pragma unroll
        for (int j = 0; j < 4; j++) acc[i][j] = 0.f;

    for (int k0 = 0; k0 < TT; k0 += 16) {
        const float* ap = Abase + (size_t)(m0 + arow) * TT + k0 + acol;
        float4 a0 = *(const float4*)&ap[0];
        float4 a1 = *(const float4*)&ap[4];
        float4 bv = *(const float4*)&Bbase[(size_t)(k0 + brow) * DDM + bcol];
        sA[acol + 0][arow] = a0.x;
        sA[acol + 1][arow] = a0.y;
        sA[acol + 2][arow] = a0.z;
        sA[acol + 3][arow] = a0.w;
        sA[acol + 4][arow] = a1.x;
        sA[acol + 5][arow] = a1.y;
        sA[acol + 6][arow] = a1.z;
        sA[acol + 7][arow] = a1.w;
        *(float4*)&sB[brow][bcol] = bv;
        __syncthreads();

        #pragma unroll
        for (int kk = 0; kk < 16; kk++) {
            float ar[8];
            *(float4*)&ar[0] = *(const float4*)&sA[kk][tr];
            *(float4*)&ar[4] = *(const float4*)&sA[kk][tr + 4];
            float4 br = *(const float4*)&sB[kk][tc];
            #pragma unroll
            for (int i = 0; i < 8; i++) {
                acc[i][0] = fmaf(ar[i], br.x, acc[i][0]);
                acc[i][1] = fmaf(ar[i], br.y, acc[i][1]);
                acc[i][2] = fmaf(ar[i], br.z, acc[i][2]);
                acc[i][3] = fmaf(ar[i], br.w, acc[i][3]);
            }
        }
        __syncthreads();
    }

    float* Cdst = g_ctx + (size_t)b * TT * DDM + h * HDM;
    #pragma unroll
    for (int i = 0; i < 8; i++) {
        *(float4*)&Cdst[(size_t)(m0 + tr + i) * DDM + tc] =
            make_float4(acc[i][0], acc[i][1], acc[i][2], acc[i][3]);
    }
}

// ---------------------------------------------------------------------------
// Launch — kernel launches ONLY (graph-capture safe, no CUDA queries/APIs)
// ---------------------------------------------------------------------------
extern "C" void kernel_launch(void* const* d_in, const int* in_sizes, int n_in,
                              void* d_out, int out_size)
{
    const float* q  = (const float*)d_in[0];
    const float* k  = (const float*)d_in[1];
    const float* v  = (const float*)d_in[2];
    const float* Wq = (const float*)d_in[3];
    const float* bq = (const float*)d_in[4];
    const float* Wk = (const float*)d_in[5];
    const float* bk = (const float*)d_in[6];
    // d_in[7] = Wv, d_in[8] = bv : intentionally unused (reference bug preserved)
    const float* Wc = (const float*)d_in[9];
    const float* bc = (const float*)d_in[10];
    float* out = (float*)d_out;

    dim3 gProj(DDM / 128, MM / 128);   // (4, 64)

    // Projections (note: vp uses Wk/bk on purpose — reference bug preserved)
    mha_gemm512_bias<<<gProj, 256>>>(q, 0, Wq, bq, nullptr, 1);   // -> g_qp
    mha_gemm512_bias<<<gProj, 256>>>(k, 0, Wk, bk, nullptr, 2);   // -> g_kp
    mha_gemm512_bias<<<gProj, 256>>>(v, 0, Wk, bk, nullptr, 3);   // -> g_vp

    // Scores + softmax over heads
    mha_scores_softmax<<<dim3(TT / 64, TT / 32, BB), 256>>>();

    // Context: batched GEMM over (b,h)
    mha_ctx<<<dim3(TT / 128, BB * HH), 256>>>();

    // Output projection: g_ctx @ Wc + bc -> d_out
    mha_gemm512_bias<<<gProj, 256>>>(nullptr, 4, Wc, bc, out, 0);
}

// round 6
// speedup vs baseline: 2.4489x; 2.4489x over previous
#include <cuda_runtime.h>
#include <math.h>
#include <stdint.h>

// Problem constants
#define BB  4
#define TT  2048
#define DDM 512
#define HH  8
#define HDM 64
#define MM  (BB*TT)

// ---------------------------------------------------------------------------
// Scratch
// ---------------------------------------------------------------------------
static __device__ float g_qp [MM * DDM];
static __device__ float g_kp [MM * DDM];
static __device__ float g_vp [MM * DDM];
static __device__ float g_ctx[MM * DDM];

__device__ __forceinline__ const float* sel_src(int s, const float* ext) {
    switch (s) { case 1: return g_qp; case 2: return g_kp; case 3: return g_vp;
                 case 4: return g_ctx; default: return ext; }
}
__device__ __forceinline__ float* sel_dst(int s, float* ext) {
    switch (s) { case 1: return g_qp; case 2: return g_kp; case 3: return g_vp;
                 case 4: return g_ctx; default: return ext; }
}

// ---------------------------------------------------------------------------
// tf32 helpers (plain sm_80+ PTX — valid at compute_100)
// ---------------------------------------------------------------------------
__device__ __forceinline__ uint32_t tf32u(float x) {
    uint32_t r;
    asm("cvt.rna.tf32.f32 %0, %1;" : "=r"(r) : "f"(x));
    return r;
}
__device__ __forceinline__ float tf32f(float x) {
    return __uint_as_float(tf32u(x));
}

// D(4xf32) += A(4xtf32) * B(2xtf32), m16n8k8
#define MMA8(d, a, b) \
    asm volatile("mma.sync.aligned.m16n8k8.row.col.f32.tf32.tf32.f32 " \
        "{%0,%1,%2,%3}, {%4,%5,%6,%7}, {%8,%9}, {%0,%1,%2,%3};" \
        : "+f"((d)[0]), "+f"((d)[1]), "+f"((d)[2]), "+f"((d)[3]) \
        : "r"((a)[0]), "r"((a)[1]), "r"((a)[2]), "r"((a)[3]), \
          "r"((b)[0]), "r"((b)[1]))

// ---------------------------------------------------------------------------
// Kernel 1: projection GEMM  C[8192,512] = A @ W + bias   (tf32 HMMA)
// Block tile 128x128, BK=32, 256 thr = 8 warps (2m x 4n), warp tile 64x32.
// smem layouts are fragment-friendly (conflict-free frag loads):
//   sA[s4][m 128][12]  (k-within-8 at stride 1, row stride 12)
//   sB[s4][kk 8][136]  (n at stride 1, kk stride 136)
// ---------------------------------------------------------------------------
__global__ __launch_bounds__(256)
void proj_mma(const float* __restrict__ Aext, int Asel,
              const float* __restrict__ W,
              const float* __restrict__ bias,
              float* __restrict__ Cext, int Csel)
{
    const float* A = sel_src(Asel, Aext);
    float*       C = sel_dst(Csel, Cext);

    __shared__ float sA[4 * 128 * 12];   // 24 KB
    __shared__ float sB[4 * 8 * 136];    // 17.4 KB

    const int tid  = threadIdx.x;
    const int wid  = tid >> 5;
    const int lane = tid & 31;
    const int g    = lane >> 2;       // group id 0..7
    const int c    = lane & 3;        // thread-in-group 0..3
    const int wm   = wid >> 2;        // 0..1
    const int wn   = wid & 3;         // 0..3
    const int m0   = blockIdx.y * 128;
    const int n0   = blockIdx.x * 128;

    // staging maps (per thread: 4 A-float4s, 4 B-float4s per BK iter)
    int ar[4], ac4[4], bk_[4], bn4[4];
    #pragma unroll
    for (int i = 0; i < 4; i++) {
        int idx = tid + 256 * i;
        ar[i]  = idx >> 3;      ac4[i] = idx & 7;     // A: row 0..127, c4 0..7
        bk_[i] = idx >> 5;      bn4[i] = idx & 31;    // B: k 0..31, n4 0..31
    }

    float df[4][4][4];
    #pragma unroll
    for (int mt = 0; mt < 4; mt++)
        #pragma unroll
        for (int nt = 0; nt < 4; nt++)
            #pragma unroll
            for (int j = 0; j < 4; j++) df[mt][nt][j] = 0.f;

    float4 pa[4], pb[4];
    #pragma unroll
    for (int i = 0; i < 4; i++) {
        pa[i] = *(const float4*)&A[(size_t)(m0 + ar[i]) * DDM + ac4[i] * 4];
        pb[i] = *(const float4*)&W[(size_t)bk_[i] * DDM + n0 + bn4[i] * 4];
    }

    for (int it = 0; it < 16; it++) {
        // store staged tiles (tf32-rounded)
        #pragma unroll
        for (int i = 0; i < 4; i++) {
            float4 v = pa[i];
            v.x = tf32f(v.x); v.y = tf32f(v.y); v.z = tf32f(v.z); v.w = tf32f(v.w);
            *(float4*)&sA[((ac4[i] >> 1) * 128 + ar[i]) * 12 + (ac4[i] & 1) * 4] = v;
            float4 u = pb[i];
            u.x = tf32f(u.x); u.y = tf32f(u.y); u.z = tf32f(u.z); u.w = tf32f(u.w);
            *(float4*)&sB[((bk_[i] >> 3) * 8 + (bk_[i] & 7)) * 136 + bn4[i] * 4] = u;
        }
        __syncthreads();

        if (it < 15) {
            const int kc = (it + 1) * 32;
            #pragma unroll
            for (int i = 0; i < 4; i++) {
                pa[i] = *(const float4*)&A[(size_t)(m0 + ar[i]) * DDM + kc + ac4[i] * 4];
                pb[i] = *(const float4*)&W[(size_t)(kc + bk_[i]) * DDM + n0 + bn4[i] * 4];
            }
        }

        #pragma unroll
        for (int s4 = 0; s4 < 4; s4++) {
            uint32_t bf[4][2];
            #pragma unroll
            for (int nt = 0; nt < 4; nt++) {
                int n = wn * 32 + nt * 8 + g;
                bf[nt][0] = __float_as_uint(sB[(s4 * 8 + c)     * 136 + n]);
                bf[nt][1] = __float_as_uint(sB[(s4 * 8 + c + 4) * 136 + n]);
            }
            #pragma unroll
            for (int mt = 0; mt < 4; mt++) {
                int m = wm * 64 + mt * 16 + g;
                uint32_t af[4];
                af[0] = __float_as_uint(sA[(s4 * 128 + m)     * 12 + c]);
                af[1] = __float_as_uint(sA[(s4 * 128 + m + 8) * 12 + c]);
                af[2] = __float_as_uint(sA[(s4 * 128 + m)     * 12 + c + 4]);
                af[3] = __float_as_uint(sA[(s4 * 128 + m + 8) * 12 + c + 4]);
                #pragma unroll
                for (int nt = 0; nt < 4; nt++)
                    MMA8(df[mt][nt], af, bf[nt]);
            }
        }
        __syncthreads();
    }

    // epilogue: + bias, write float2 pairs
    #pragma unroll
    for (int nt = 0; nt < 4; nt++) {
        const int col = n0 + wn * 32 + nt * 8 + 2 * c;
        const float b0 = bias[col], b1 = bias[col + 1];
        #pragma unroll
        for (int mt = 0; mt < 4; mt++) {
            const int row = m0 + wm * 64 + mt * 16 + g;
            float2 o0 = make_float2(df[mt][nt][0] + b0, df[mt][nt][1] + b1);
            float2 o1 = make_float2(df[mt][nt][2] + b0, df[mt][nt][3] + b1);
            *(float2*)&C[(size_t)row * DDM + col]       = o0;
            *(float2*)&C[(size_t)(row + 8) * DDM + col] = o1;
        }
    }
}

// ---------------------------------------------------------------------------
// Kernel 2: fused attention (scores + softmax-over-heads + ctx), tf32 HMMA.
// Block = 32 q-rows of one batch; warp w = head w. Q frags persistent in regs.
// Loop over k in chunks of 32: stage K/V to smem, S = Q@K^T (mma),
// exchange via smem, 8-head softmax per (q,k), attn@V (mma) into ctx regs.
// attn never touches gmem.
// ---------------------------------------------------------------------------
#define SKS 516                    // sK row stride (conflict-free B-frags)
#define SVS 520                    // sV row stride
#define SES 36                     // sE k stride
#define SEH (32 * SES)             // sE head stride
#define FA_SMEM_BYTES ((32*SKS + 32*SVS + 8*SEH) * 4)

__global__ __launch_bounds__(256)
void fa_kernel(void)
{
    extern __shared__ float sm[];
    float* sK = sm;                       // [32][516]
    float* sV = sm + 32 * SKS;            // [32][520]
    float* sE = sm + 32 * SKS + 32 * SVS; // [8][32][36]

    const int tid  = threadIdx.x;
    const int w    = tid >> 5;            // warp = head
    const int lane = tid & 31;
    const int g    = lane >> 2;
    const int c    = lane & 3;
    const int q0   = blockIdx.x * 32;
    const size_t bT = (size_t)blockIdx.y * TT;

    // ---- load Q fragments (persistent): Q_w[32 x 64], tf32-rounded ----
    uint32_t qf[2][8][4];
    #pragma unroll
    for (int mt = 0; mt < 2; mt++) {
        const size_t r0 = bT + q0 + mt * 16 + g;
        #pragma unroll
        for (int ds = 0; ds < 8; ds++) {
            const int col = w * HDM + ds * 8 + c;
            qf[mt][ds][0] = tf32u(g_qp[r0 * DDM + col]);
            qf[mt][ds][1] = tf32u(g_qp[(r0 + 8) * DDM + col]);
            qf[mt][ds][2] = tf32u(g_qp[r0 * DDM + col + 4]);
            qf[mt][ds][3] = tf32u(g_qp[(r0 + 8) * DDM + col + 4]);
        }
    }

    float ctxf[2][8][4];
    #pragma unroll
    for (int mt = 0; mt < 2; mt++)
        #pragma unroll
        for (int nt = 0; nt < 8; nt++)
            #pragma unroll
            for (int j = 0; j < 4; j++) ctxf[mt][nt][j] = 0.f;

    for (int kt = 0; kt < TT / 32; kt++) {
        const int k0 = kt * 32;
        __syncthreads();   // previous chunk's smem readers done

        // ---- stage K,V chunk [32 x 512] each, coalesced, tf32-rounded ----
        #pragma unroll
        for (int i = 0; i < 16; i++) {
            const int idx = tid + 256 * i;
            const int r = idx >> 7, c4 = idx & 127;
            const size_t go = (bT + k0 + r) * DDM + c4 * 4;
            float4 kv = *(const float4*)&g_kp[go];
            kv.x = tf32f(kv.x); kv.y = tf32f(kv.y); kv.z = tf32f(kv.z); kv.w = tf32f(kv.w);
            *(float4*)&sK[r * SKS + c4 * 4] = kv;
            float4 vv = *(const float4*)&g_vp[go];
            vv.x = tf32f(vv.x); vv.y = tf32f(vv.y); vv.z = tf32f(vv.z); vv.w = tf32f(vv.w);
            *(float4*)&sV[r * SVS + c4 * 4] = vv;
        }
        __syncthreads();

        // ---- S = Q_w @ K_w^T : [32 q x 32 k] ----
        float sf[2][4][4];
        #pragma unroll
        for (int mt = 0; mt < 2; mt++)
            #pragma unroll
            for (int nt = 0; nt < 4; nt++)
                #pragma unroll
                for (int j = 0; j < 4; j++) sf[mt][nt][j] = 0.f;

        #pragma unroll
        for (int ds = 0; ds < 8; ds++) {
            uint32_t bf[4][2];
            #pragma unroll
            for (int nt = 0; nt < 4; nt++) {
                const int krow = nt * 8 + g;
                const int dcol = w * HDM + ds * 8 + c;
                bf[nt][0] = __float_as_uint(sK[krow * SKS + dcol]);
                bf[nt][1] = __float_as_uint(sK[krow * SKS + dcol + 4]);
            }
            #pragma unroll
            for (int mt = 0; mt < 2; mt++)
                #pragma unroll
                for (int nt = 0; nt < 4; nt++)
                    MMA8(sf[mt][nt], qf[mt][ds], bf[nt]);
        }

        // ---- write S frags to exchange buffer sE[head][q][k] ----
        #pragma unroll
        for (int mt = 0; mt < 2; mt++)
            #pragma unroll
            for (int nt = 0; nt < 4; nt++) {
                float* e = &sE[w * SEH + (mt * 16 + g) * SES + nt * 8 + 2 * c];
                *(float2*)e             = make_float2(sf[mt][nt][0], sf[mt][nt][1]);
                *(float2*)(e + 8 * SES) = make_float2(sf[mt][nt][2], sf[mt][nt][3]);
            }
        __syncthreads();

        // ---- softmax over heads: each thread owns 4 (q,k) elements ----
        {
            const int q  = tid >> 3;
            const int kb = (tid & 7) * 4;
            float4 v[8];
            #pragma unroll
            for (int h = 0; h < 8; h++)
                v[h] = *(const float4*)&sE[h * SEH + q * SES + kb];
            #pragma unroll
            for (int j = 0; j < 4; j++) {
                float* vj0 = &v[0].x;   // component j of v[h] accessed below
                float m = ((float*)&v[0])[j];
                #pragma unroll
                for (int h = 1; h < 8; h++) m = fmaxf(m, ((float*)&v[h])[j]);
                float s = 0.f;
                #pragma unroll
                for (int h = 0; h < 8; h++) {
                    float e = __expf((((float*)&v[h])[j] - m) * 0.125f);
                    ((float*)&v[h])[j] = e; s += e;
                }
                const float inv = 1.f / s;
                #pragma unroll
                for (int h = 0; h < 8; h++) ((float*)&v[h])[j] *= inv;
                (void)vj0;
            }
            #pragma unroll
            for (int h = 0; h < 8; h++) {
                float4 o = v[h];
                o.x = tf32f(o.x); o.y = tf32f(o.y); o.z = tf32f(o.z); o.w = tf32f(o.w);
                *(float4*)&sE[h * SEH + q * SES + kb] = o;
            }
        }
        __syncthreads();

        // ---- ctx += attn_w[32 x 32] @ V_w[32 x 64] ----
        #pragma unroll
        for (int ks = 0; ks < 4; ks++) {
            uint32_t af[2][4];
            #pragma unroll
            for (int mt = 0; mt < 2; mt++) {
                const float* a = &sE[w * SEH + (mt * 16 + g) * SES + ks * 8 + c];
                af[mt][0] = __float_as_uint(a[0]);
                af[mt][1] = __float_as_uint(a[8 * SES]);
                af[mt][2] = __float_as_uint(a[4]);
                af[mt][3] = __float_as_uint(a[8 * SES + 4]);
            }
            uint32_t vf[8][2];
            #pragma unroll
            for (int nt = 0; nt < 8; nt++) {
                const int dcol = w * HDM + nt * 8 + g;
                vf[nt][0] = __float_as_uint(sV[(ks * 8 + c) * SVS + dcol]);
                vf[nt][1] = __float_as_uint(sV[(ks * 8 + c + 4) * SVS + dcol]);
            }
            #pragma unroll
            for (int mt = 0; mt < 2; mt++)
                #pragma unroll
                for (int nt = 0; nt < 8; nt++)
                    MMA8(ctxf[mt][nt], af[mt], vf[nt]);
        }
    }

    // ---- epilogue: ctx -> g_ctx[b, q, w*64 + d] ----
    #pragma unroll
    for (int mt = 0; mt < 2; mt++) {
        const size_t row = bT + q0 + mt * 16 + g;
        #pragma unroll
        for (int nt = 0; nt < 8; nt++) {
            const int dcol = w * HDM + nt * 8 + 2 * c;
            *(float2*)&g_ctx[row * DDM + dcol] =
                make_float2(ctxf[mt][nt][0], ctxf[mt][nt][1]);
            *(float2*)&g_ctx[(row + 8) * DDM + dcol] =
                make_float2(ctxf[mt][nt][2], ctxf[mt][nt][3]);
        }
    }
}

// ---------------------------------------------------------------------------
// Launch — kernel launches only (+ idempotent smem attribute set)
// ---------------------------------------------------------------------------
extern "C" void kernel_launch(void* const* d_in, const int* in_sizes, int n_in,
                              void* d_out, int out_size)
{
    const float* q  = (const float*)d_in[0];
    const float* k  = (const float*)d_in[1];
    const float* v  = (const float*)d_in[2];
    const float* Wq = (const float*)d_in[3];
    const float* bq = (const float*)d_in[4];
    const float* Wk = (const float*)d_in[5];
    const float* bk = (const float*)d_in[6];
    // d_in[7]=Wv, d_in[8]=bv intentionally unused (reference bug preserved)
    const float* Wc = (const float*)d_in[9];
    const float* bc = (const float*)d_in[10];
    float* out = (float*)d_out;

    cudaFuncSetAttribute(fa_kernel,
                         cudaFuncAttributeMaxDynamicSharedMemorySize,
                         FA_SMEM_BYTES);

    dim3 gProj(DDM / 128, MM / 128);   // (4, 64)

    proj_mma<<<gProj, 256>>>(q, 0, Wq, bq, nullptr, 1);   // -> g_qp
    proj_mma<<<gProj, 256>>>(k, 0, Wk, bk, nullptr, 2);   // -> g_kp
    proj_mma<<<gProj, 256>>>(v, 0, Wk, bk, nullptr, 3);   // -> g_vp (Wk/bk: bug preserved)

    fa_kernel<<<dim3(TT / 32, BB), 256, FA_SMEM_BYTES>>>();

    proj_mma<<<gProj, 256>>>(nullptr, 4, Wc, bc, out, 0); // g_ctx @ Wc + bc -> out
}

// round 7
// speedup vs baseline: 2.6056x; 1.0640x over previous
#include <cuda_runtime.h>
#include <math.h>
#include <stdint.h>

// Problem constants
#define BB  4
#define TT  2048
#define DDM 512
#define HH  8
#define HDM 64
#define MM  (BB*TT)

// ---------------------------------------------------------------------------
// Scratch
// ---------------------------------------------------------------------------
static __device__ float g_qp [MM * DDM];
static __device__ float g_kp [MM * DDM];
static __device__ float g_vp [MM * DDM];
static __device__ float g_ctx[MM * DDM];

__device__ __forceinline__ const float* sel_src(int s, const float* ext) {
    switch (s) { case 1: return g_qp; case 2: return g_kp; case 3: return g_vp;
                 case 4: return g_ctx; default: return ext; }
}
__device__ __forceinline__ float* sel_dst(int s, float* ext) {
    switch (s) { case 1: return g_qp; case 2: return g_kp; case 3: return g_vp;
                 case 4: return g_ctx; default: return ext; }
}

// ---------------------------------------------------------------------------
// tf32 helpers (plain sm_80+ PTX — valid at compute_100)
// ---------------------------------------------------------------------------
__device__ __forceinline__ uint32_t tf32u(float x) {
    uint32_t r;
    asm("cvt.rna.tf32.f32 %0, %1;" : "=r"(r) : "f"(x));
    return r;
}
__device__ __forceinline__ float tf32f(float x) {
    return __uint_as_float(tf32u(x));
}

// D(4xf32) += A(4xtf32) * B(2xtf32), m16n8k8
#define MMA8(d, a, b) \
    asm volatile("mma.sync.aligned.m16n8k8.row.col.f32.tf32.tf32.f32 " \
        "{%0,%1,%2,%3}, {%4,%5,%6,%7}, {%8,%9}, {%0,%1,%2,%3};" \
        : "+f"((d)[0]), "+f"((d)[1]), "+f"((d)[2]), "+f"((d)[3]) \
        : "r"((a)[0]), "r"((a)[1]), "r"((a)[2]), "r"((a)[3]), \
          "r"((b)[0]), "r"((b)[1]))

// ---------------------------------------------------------------------------
// Kernel 1: projection GEMM  C[8192,512] = A @ W + bias   (tf32 HMMA)
// Unchanged from R6 (measured ~18us each).
// ---------------------------------------------------------------------------
__global__ __launch_bounds__(256)
void proj_mma(const float* __restrict__ Aext, int Asel,
              const float* __restrict__ W,
              const float* __restrict__ bias,
              float* __restrict__ Cext, int Csel)
{
    const float* A = sel_src(Asel, Aext);
    float*       C = sel_dst(Csel, Cext);

    __shared__ float sA[4 * 128 * 12];   // 24 KB
    __shared__ float sB[4 * 8 * 136];    // 17.4 KB

    const int tid  = threadIdx.x;
    const int wid  = tid >> 5;
    const int lane = tid & 31;
    const int g    = lane >> 2;
    const int c    = lane & 3;
    const int wm   = wid >> 2;
    const int wn   = wid & 3;
    const int m0   = blockIdx.y * 128;
    const int n0   = blockIdx.x * 128;

    int ar[4], ac4[4], bk_[4], bn4[4];
    #pragma unroll
    for (int i = 0; i < 4; i++) {
        int idx = tid + 256 * i;
        ar[i]  = idx >> 3;      ac4[i] = idx & 7;
        bk_[i] = idx >> 5;      bn4[i] = idx & 31;
    }

    float df[4][4][4];
    #pragma unroll
    for (int mt = 0; mt < 4; mt++)
        #pragma unroll
        for (int nt = 0; nt < 4; nt++)
            #pragma unroll
            for (int j = 0; j < 4; j++) df[mt][nt][j] = 0.f;

    float4 pa[4], pb[4];
    #pragma unroll
    for (int i = 0; i < 4; i++) {
        pa[i] = *(const float4*)&A[(size_t)(m0 + ar[i]) * DDM + ac4[i] * 4];
        pb[i] = *(const float4*)&W[(size_t)bk_[i] * DDM + n0 + bn4[i] * 4];
    }

    for (int it = 0; it < 16; it++) {
        #pragma unroll
        for (int i = 0; i < 4; i++) {
            float4 v = pa[i];
            v.x = tf32f(v.x); v.y = tf32f(v.y); v.z = tf32f(v.z); v.w = tf32f(v.w);
            *(float4*)&sA[((ac4[i] >> 1) * 128 + ar[i]) * 12 + (ac4[i] & 1) * 4] = v;
            float4 u = pb[i];
            u.x = tf32f(u.x); u.y = tf32f(u.y); u.z = tf32f(u.z); u.w = tf32f(u.w);
            *(float4*)&sB[((bk_[i] >> 3) * 8 + (bk_[i] & 7)) * 136 + bn4[i] * 4] = u;
        }
        __syncthreads();

        if (it < 15) {
            const int kc = (it + 1) * 32;
            #pragma unroll
            for (int i = 0; i < 4; i++) {
                pa[i] = *(const float4*)&A[(size_t)(m0 + ar[i]) * DDM + kc + ac4[i] * 4];
                pb[i] = *(const float4*)&W[(size_t)(kc + bk_[i]) * DDM + n0 + bn4[i] * 4];
            }
        }

        #pragma unroll
        for (int s4 = 0; s4 < 4; s4++) {
            uint32_t bf[4][2];
            #pragma unroll
            for (int nt = 0; nt < 4; nt++) {
                int n = wn * 32 + nt * 8 + g;
                bf[nt][0] = __float_as_uint(sB[(s4 * 8 + c)     * 136 + n]);
                bf[nt][1] = __float_as_uint(sB[(s4 * 8 + c + 4) * 136 + n]);
            }
            #pragma unroll
            for (int mt = 0; mt < 4; mt++) {
                int m = wm * 64 + mt * 16 + g;
                uint32_t af[4];
                af[0] = __float_as_uint(sA[(s4 * 128 + m)     * 12 + c]);
                af[1] = __float_as_uint(sA[(s4 * 128 + m + 8) * 12 + c]);
                af[2] = __float_as_uint(sA[(s4 * 128 + m)     * 12 + c + 4]);
                af[3] = __float_as_uint(sA[(s4 * 128 + m + 8) * 12 + c + 4]);
                #pragma unroll
                for (int nt = 0; nt < 4; nt++)
                    MMA8(df[mt][nt], af, bf[nt]);
            }
        }
        __syncthreads();
    }

    #pragma unroll
    for (int nt = 0; nt < 4; nt++) {
        const int col = n0 + wn * 32 + nt * 8 + 2 * c;
        const float b0 = bias[col], b1 = bias[col + 1];
        #pragma unroll
        for (int mt = 0; mt < 4; mt++) {
            const int row = m0 + wm * 64 + mt * 16 + g;
            float2 o0 = make_float2(df[mt][nt][0] + b0, df[mt][nt][1] + b1);
            float2 o1 = make_float2(df[mt][nt][2] + b0, df[mt][nt][3] + b1);
            *(float2*)&C[(size_t)row * DDM + col]       = o0;
            *(float2*)&C[(size_t)(row + 8) * DDM + col] = o1;
        }
    }
}

// ---------------------------------------------------------------------------
// Kernel 2: fused attention, tf32 HMMA, 512 threads / 16 warps.
// warp = (half, head): head w = wid&7, q-half = wid>>3 (16 q-rows per warp).
// Q frags persistent in regs (32 regs). K/V chunk (32 rows) staged in smem.
// Per chunk: S = Q@K^T -> exchange smem -> 8-head softmax -> attn@V.
// __launch_bounds__(512) caps regs at 128 -> full RF, 16 warps resident.
// ---------------------------------------------------------------------------
#define SKS 516                    // sK row stride
#define SVS 520                    // sV row stride
#define SES 36                     // sE q-row stride (32 k + 4 pad)
#define SEH (32 * SES)             // sE head stride
#define FA_SMEM_BYTES ((32*SKS + 32*SVS + 8*SEH) * 4)

__global__ __launch_bounds__(512, 1)
void fa_kernel(void)
{
    extern __shared__ float sm[];
    float* sK = sm;                       // [32][516]
    float* sV = sm + 32 * SKS;            // [32][520]
    float* sE = sm + 32 * SKS + 32 * SVS; // [8][32][36]

    const int tid  = threadIdx.x;
    const int wid  = tid >> 5;
    const int w    = wid & 7;             // head
    const int half = wid >> 3;            // q-half: rows half*16 .. +15
    const int lane = tid & 31;
    const int g    = lane >> 2;
    const int c    = lane & 3;
    const int q0   = blockIdx.x * 32;
    const size_t bT = (size_t)blockIdx.y * TT;

    // ---- persistent Q fragments: 16 q-rows x 64 d for head w ----
    uint32_t qf[8][4];
    {
        const size_t r0 = bT + q0 + half * 16 + g;
        #pragma unroll
        for (int ds = 0; ds < 8; ds++) {
            const int col = w * HDM + ds * 8 + c;
            qf[ds][0] = tf32u(g_qp[r0 * DDM + col]);
            qf[ds][1] = tf32u(g_qp[(r0 + 8) * DDM + col]);
            qf[ds][2] = tf32u(g_qp[r0 * DDM + col + 4]);
            qf[ds][3] = tf32u(g_qp[(r0 + 8) * DDM + col + 4]);
        }
    }

    float ctxf[8][4];
    #pragma unroll
    for (int nt = 0; nt < 8; nt++)
        #pragma unroll
        for (int j = 0; j < 4; j++) ctxf[nt][j] = 0.f;

    for (int kt = 0; kt < TT / 32; kt++) {
        const int k0 = kt * 32;
        __syncthreads();   // previous chunk's smem readers done

        // ---- stage K,V chunk [32 x 512] each, 512 threads, tf32-rounded ----
        #pragma unroll
        for (int i = 0; i < 8; i++) {
            const int idx = tid + 512 * i;
            const int r = idx >> 7, c4 = idx & 127;
            const size_t go = (bT + k0 + r) * DDM + c4 * 4;
            float4 kv = *(const float4*)&g_kp[go];
            kv.x = tf32f(kv.x); kv.y = tf32f(kv.y); kv.z = tf32f(kv.z); kv.w = tf32f(kv.w);
            *(float4*)&sK[r * SKS + c4 * 4] = kv;
            float4 vv = *(const float4*)&g_vp[go];
            vv.x = tf32f(vv.x); vv.y = tf32f(vv.y); vv.z = tf32f(vv.z); vv.w = tf32f(vv.w);
            *(float4*)&sV[r * SVS + c4 * 4] = vv;
        }
        __syncthreads();

        // ---- S = Q_w[16x64] @ K_w^T[64x32] ----
        float sf[4][4];
        #pragma unroll
        for (int nt = 0; nt < 4; nt++)
            #pragma unroll
            for (int j = 0; j < 4; j++) sf[nt][j] = 0.f;

        #pragma unroll
        for (int ds = 0; ds < 8; ds++) {
            uint32_t bf[4][2];
            #pragma unroll
            for (int nt = 0; nt < 4; nt++) {
                const int krow = nt * 8 + g;
                const int dcol = w * HDM + ds * 8 + c;
                bf[nt][0] = __float_as_uint(sK[krow * SKS + dcol]);
                bf[nt][1] = __float_as_uint(sK[krow * SKS + dcol + 4]);
            }
            #pragma unroll
            for (int nt = 0; nt < 4; nt++)
                MMA8(sf[nt], qf[ds], bf[nt]);
        }

        // ---- write S frags to exchange buffer sE[head][q][k] ----
        #pragma unroll
        for (int nt = 0; nt < 4; nt++) {
            float* e = &sE[w * SEH + (half * 16 + g) * SES + nt * 8 + 2 * c];
            *(float2*)e             = make_float2(sf[nt][0], sf[nt][1]);
            *(float2*)(e + 8 * SES) = make_float2(sf[nt][2], sf[nt][3]);
        }
        __syncthreads();

        // ---- softmax over heads: each thread owns 2 (q,k) elements ----
        {
            const int q  = tid >> 4;            // 0..31
            const int kb = (tid & 15) * 2;      // 0..30
            float2 v[8];
            #pragma unroll
            for (int h = 0; h < 8; h++)
                v[h] = *(const float2*)&sE[h * SEH + q * SES + kb];
            #pragma unroll
            for (int j = 0; j < 2; j++) {
                float m = ((float*)&v[0])[j];
                #pragma unroll
                for (int h = 1; h < 8; h++) m = fmaxf(m, ((float*)&v[h])[j]);
                float s = 0.f;
                #pragma unroll
                for (int h = 0; h < 8; h++) {
                    float e = __expf((((float*)&v[h])[j] - m) * 0.125f);
                    ((float*)&v[h])[j] = e; s += e;
                }
                const float inv = 1.f / s;
                #pragma unroll
                for (int h = 0; h < 8; h++) ((float*)&v[h])[j] *= inv;
            }
            #pragma unroll
            for (int h = 0; h < 8; h++) {
                float2 o = v[h];
                o.x = tf32f(o.x); o.y = tf32f(o.y);
                *(float2*)&sE[h * SEH + q * SES + kb] = o;
            }
        }
        __syncthreads();

        // ---- ctx += attn_w[16x32] @ V_w[32x64] ----
        #pragma unroll
        for (int ks = 0; ks < 4; ks++) {
            uint32_t af[4];
            {
                const float* a = &sE[w * SEH + (half * 16 + g) * SES + ks * 8 + c];
                af[0] = __float_as_uint(a[0]);
                af[1] = __float_as_uint(a[8 * SES]);
                af[2] = __float_as_uint(a[4]);
                af[3] = __float_as_uint(a[8 * SES + 4]);
            }
            uint32_t vf[8][2];
            #pragma unroll
            for (int nt = 0; nt < 8; nt++) {
                const int dcol = w * HDM + nt * 8 + g;
                vf[nt][0] = __float_as_uint(sV[(ks * 8 + c) * SVS + dcol]);
                vf[nt][1] = __float_as_uint(sV[(ks * 8 + c + 4) * SVS + dcol]);
            }
            #pragma unroll
            for (int nt = 0; nt < 8; nt++)
                MMA8(ctxf[nt], af, vf[nt]);
        }
    }

    // ---- epilogue: ctx -> g_ctx[b, q, w*64 + d] ----
    {
        const size_t row = bT + q0 + half * 16 + g;
        #pragma unroll
        for (int nt = 0; nt < 8; nt++) {
            const int dcol = w * HDM + nt * 8 + 2 * c;
            *(float2*)&g_ctx[row * DDM + dcol] =
                make_float2(ctxf[nt][0], ctxf[nt][1]);
            *(float2*)&g_ctx[(row + 8) * DDM + dcol] =
                make_float2(ctxf[nt][2], ctxf[nt][3]);
        }
    }
}

// ---------------------------------------------------------------------------
// Launch — kernel launches only (+ idempotent smem attribute set)
// ---------------------------------------------------------------------------
extern "C" void kernel_launch(void* const* d_in, const int* in_sizes, int n_in,
                              void* d_out, int out_size)
{
    const float* q  = (const float*)d_in[0];
    const float* k  = (const float*)d_in[1];
    const float* v  = (const float*)d_in[2];
    const float* Wq = (const float*)d_in[3];
    const float* bq = (const float*)d_in[4];
    const float* Wk = (const float*)d_in[5];
    const float* bk = (const float*)d_in[6];
    // d_in[7]=Wv, d_in[8]=bv intentionally unused (reference bug preserved)
    const float* Wc = (const float*)d_in[9];
    const float* bc = (const float*)d_in[10];
    float* out = (float*)d_out;

    cudaFuncSetAttribute(fa_kernel,
                         cudaFuncAttributeMaxDynamicSharedMemorySize,
                         FA_SMEM_BYTES);

    dim3 gProj(DDM / 128, MM / 128);   // (4, 64)

    proj_mma<<<gProj, 256>>>(q, 0, Wq, bq, nullptr, 1);   // -> g_qp
    proj_mma<<<gProj, 256>>>(k, 0, Wk, bk, nullptr, 2);   // -> g_kp
    proj_mma<<<gProj, 256>>>(v, 0, Wk, bk, nullptr, 3);   // -> g_vp (Wk/bk: bug preserved)

    fa_kernel<<<dim3(TT / 32, BB), 512, FA_SMEM_BYTES>>>();

    proj_mma<<<gProj, 256>>>(nullptr, 4, Wc, bc, out, 0); // g_ctx @ Wc + bc -> out
}